// round 15
// baseline (speedup 1.0000x reference)
#include <cuda_runtime.h>
#include <cuda_fp16.h>
#include <cstdint>

#define C 256            // IN_C == OUT_C == 256
#define MAX_NODES 50048
#define MAX_CLUSTERS 128
#define CAP 64           // max in-degree bucket (Poisson(5.4) -> max ~25)

// ---- GEMM tiling (fp16 m16n8k16) ----
#define BM 128           // CTA tile M (nodes)
#define BN 128           // CTA tile N (out channels)
#define BKH 64           // K halves per stage (64*2B = 128B rows)
#define NSTAGE (C / BKH) // 4
#define ROW_BYTES 144    // padded row: 9 x 16B (odd) -> conflict-free ldmatrix
#define A_BYTES (BM * ROW_BYTES)             // 18432
#define B_BYTES (BN * ROW_BYTES)             // 18432 (B stored n-major)
#define STAGE_BYTES (A_BYTES + B_BYTES)      // 36864
#define SMEM_TOTAL (2 * STAGE_BYTES)         // 73728

// Scratch (allocation-free rule: __device__ globals)
__device__ __half g_xWsh[(size_t)MAX_NODES * C]; // xW * rsqrt(deg), fp16
__device__ __half g_WhT[C * C];                  // W^T in fp16: [oc][ic]
__device__ int    g_cnt[MAX_NODES];              // intra in-degree
__device__ int    g_adj[(size_t)MAX_NODES * CAP];// per-dst src buckets
__device__ int    g_cedge[MAX_CLUSTERS];

// ---------------------------------------------------------------------------
// helpers
// ---------------------------------------------------------------------------
__device__ __forceinline__ uint32_t smem_u32(const void* p) {
    uint32_t a;
    asm("{ .reg .u64 t; cvta.to.shared.u64 t, %1; cvt.u32.u64 %0, t; }"
        : "=r"(a) : "l"(p));
    return a;
}
__device__ __forceinline__ void cp_async16(uint32_t dst, const void* src) {
    asm volatile("cp.async.cg.shared.global [%0], [%1], 16;"
                 :: "r"(dst), "l"(src) : "memory");
}
#define CP_COMMIT() asm volatile("cp.async.commit_group;" ::: "memory")
#define CP_WAIT(n)  asm volatile("cp.async.wait_group %0;" :: "n"(n) : "memory")

__device__ __forceinline__ void ldsm_x4(uint32_t& r0, uint32_t& r1,
                                        uint32_t& r2, uint32_t& r3, uint32_t addr) {
    asm volatile("ldmatrix.sync.aligned.m8n8.x4.shared.b16 {%0,%1,%2,%3}, [%4];"
                 : "=r"(r0), "=r"(r1), "=r"(r2), "=r"(r3) : "r"(addr));
}

__device__ __forceinline__ void mma_f16(float& d0, float& d1, float& d2, float& d3,
                                        uint32_t a0, uint32_t a1, uint32_t a2, uint32_t a3,
                                        uint32_t b0, uint32_t b1) {
    asm volatile(
        "mma.sync.aligned.m16n8k16.row.col.f32.f16.f16.f32 "
        "{%0,%1,%2,%3}, {%4,%5,%6,%7}, {%8,%9}, {%0,%1,%2,%3};"
        : "+f"(d0), "+f"(d1), "+f"(d2), "+f"(d3)
        : "r"(a0), "r"(a1), "r"(a2), "r"(a3), "r"(b0), "r"(b1));
}

__device__ __forceinline__ uint4 pack8h(float4 v0, float4 v1) {
    __half2 h[4];
    h[0] = __floats2half2_rn(v0.x, v0.y);
    h[1] = __floats2half2_rn(v0.z, v0.w);
    h[2] = __floats2half2_rn(v1.x, v1.y);
    h[3] = __floats2half2_rn(v1.z, v1.w);
    return *(uint4*)h;
}

// accumulate 4 half2 (a uint4) into 8 fp32 accumulators
__device__ __forceinline__ void acc8(float* a, uint4 v) {
    float2 f0 = __half22float2(*(__half2*)&v.x);
    float2 f1 = __half22float2(*(__half2*)&v.y);
    float2 f2 = __half22float2(*(__half2*)&v.z);
    float2 f3 = __half22float2(*(__half2*)&v.w);
    a[0] += f0.x; a[1] += f0.y; a[2] += f1.x; a[3] += f1.y;
    a[4] += f2.x; a[5] += f2.y; a[6] += f3.x; a[7] += f3.y;
}

// pairwise fp16 pre-add of two rows, then accumulate into fp32
__device__ __forceinline__ void acc8_pair(float* a, uint4 p, uint4 q) {
    __half2 s0 = __hadd2(*(__half2*)&p.x, *(__half2*)&q.x);
    __half2 s1 = __hadd2(*(__half2*)&p.y, *(__half2*)&q.y);
    __half2 s2 = __hadd2(*(__half2*)&p.z, *(__half2*)&q.z);
    __half2 s3 = __hadd2(*(__half2*)&p.w, *(__half2*)&q.w);
    float2 f0 = __half22float2(s0);
    float2 f1 = __half22float2(s1);
    float2 f2 = __half22float2(s2);
    float2 f3 = __half22float2(s3);
    a[0] += f0.x; a[1] += f0.y; a[2] += f1.x; a[3] += f1.y;
    a[4] += f2.x; a[5] += f2.y; a[6] += f3.x; a[7] += f3.y;
}

// ---------------------------------------------------------------------------
// Kernel 1: init counts + cluster flags  AND  W -> fp16 transposed.
// ---------------------------------------------------------------------------
#define NB_INIT 196
__global__ void init_wconv_kernel(const float* __restrict__ W, int n_nodes) {
    __shared__ float t[32][33];
    int blk = blockIdx.x;
    if (blk < NB_INIT) {
        int i = blk * 256 + threadIdx.x;
        if (i < n_nodes) g_cnt[i] = 0;
        if (i < MAX_CLUSTERS) g_cedge[i] = 0;
        return;
    }
    int wb = blk - NB_INIT;            // 0..63 -> 8x8 tiles of 32x32
    int bx = (wb & 7) * 32;            // oc tile
    int by = (wb >> 3) * 32;           // ic tile
    int tx = threadIdx.x & 31;
    int ty = threadIdx.x >> 5;         // 0..7
    for (int j = ty; j < 32; j += 8)
        t[j][tx] = W[(size_t)(by + j) * C + bx + tx];
    __syncthreads();
    for (int j = ty; j < 32; j += 8)
        g_WhT[(size_t)(bx + j) * C + by + tx] = __float2half_rn(t[tx][j]);
}

// ---------------------------------------------------------------------------
// Kernel 2: build per-dst adjacency buckets for intra-cluster edges.
// ---------------------------------------------------------------------------
__global__ void edge_build_kernel(const int* __restrict__ src,
                                  const int* __restrict__ dst,
                                  const int* __restrict__ assign,
                                  int n_edges) {
    int e = blockIdx.x * blockDim.x + threadIdx.x;
    if (e >= n_edges) return;
    int s = src[e], d = dst[e];
    int a = assign[s];
    if (a == assign[d]) {
        int pos = atomicAdd(&g_cnt[d], 1);
        if (pos < CAP) g_adj[(size_t)d * CAP + pos] = s;
        g_cedge[a] = 1;
    }
}

// ---------------------------------------------------------------------------
// Kernel 3: fp16 mma.sync GEMM. g_xWsh[row] = half((X@W)[row] * rsqrt(deg)).
// Fused fp32->fp16 A path; single __syncthreads per stage; unrolled stages.
// ---------------------------------------------------------------------------
__global__ __launch_bounds__(256, 2) void gemm_tc_kernel(
    const float* __restrict__ X, int n_nodes) {
    extern __shared__ char smem[];

    const int tid = threadIdx.x;
    const int wid = tid >> 5;
    const int lane = tid & 31;
    const int g = lane >> 2;
    const int t = lane & 3;
    const int wm = wid >> 2;
    const int wn = wid & 3;

    const int mbase = blockIdx.x * BM;
    const int nbase = blockIdx.y * BN;

    const uint32_t sbase = smem_u32(smem);

    const int a_row = lane & 15;
    const int a_byte = (lane >> 4) * 16;
    const int b_row = (lane & 7) + ((lane >> 4) * 8);
    const int b_byte = ((lane >> 3) & 1) * 16;

    const int am[4]  = { (tid + 0) >> 3, (tid + 256) >> 3, (tid + 512) >> 3, (tid + 768) >> 3 };
    const int aseg = tid & 7;

    float acc[4][4][4];
    #pragma unroll
    for (int i = 0; i < 4; i++)
        #pragma unroll
        for (int j = 0; j < 4; j++)
            #pragma unroll
            for (int k = 0; k < 4; k++) acc[i][j][k] = 0.f;

    auto ldg_a2 = [&](int ks, int c, float4& v0, float4& v1) {
        int node = mbase + am[c];
        if (node < n_nodes) {
            const float* src = X + (size_t)node * C + ks * BKH + aseg * 8;
            v0 = *(const float4*)src;
            v1 = *(const float4*)(src + 4);
        } else {
            v0 = make_float4(0.f, 0.f, 0.f, 0.f);
            v1 = v0;
        }
    };
    auto sts_a = [&](int buf, int c, float4 v0, float4 v1) {
        uint32_t off = (uint32_t)(buf * STAGE_BYTES + am[c] * ROW_BYTES + aseg * 16);
        *(uint4*)(smem + off) = pack8h(v0, v1);
    };
    auto cp_b = [&](int ks, int buf) {
        const uint32_t sB = sbase + buf * STAGE_BYTES + A_BYTES;
        #pragma unroll
        for (int p = 0; p < 4; p++) {
            int i = tid + p * 256;
            int n = i >> 3, seg = i & 7;
            const __half* src = g_WhT + (size_t)(nbase + n) * C + ks * BKH + seg * 8;
            cp_async16(sB + (uint32_t)(n * ROW_BYTES + seg * 16), src);
        }
    };
    auto compute_half = [&](uint32_t sA, uint32_t sB, int kk0) {
        #pragma unroll
        for (int kk = kk0; kk < kk0 + 32; kk += 16) {
            uint32_t af[4][4], bf[2][4];
            #pragma unroll
            for (int mi = 0; mi < 4; mi++) {
                int r = wm * 64 + mi * 16 + a_row;
                ldsm_x4(af[mi][0], af[mi][1], af[mi][2], af[mi][3],
                        sA + (uint32_t)(r * ROW_BYTES + kk * 2 + a_byte));
            }
            #pragma unroll
            for (int ni2 = 0; ni2 < 2; ni2++) {
                int n = wn * 32 + ni2 * 16 + b_row;
                ldsm_x4(bf[ni2][0], bf[ni2][1], bf[ni2][2], bf[ni2][3],
                        sB + (uint32_t)(n * ROW_BYTES + kk * 2 + b_byte));
            }
            #pragma unroll
            for (int mi = 0; mi < 4; mi++)
                #pragma unroll
                for (int ni = 0; ni < 4; ni++)
                    mma_f16(acc[mi][ni][0], acc[mi][ni][1], acc[mi][ni][2], acc[mi][ni][3],
                            af[mi][0], af[mi][1], af[mi][2], af[mi][3],
                            bf[ni >> 1][(ni & 1) * 2], bf[ni >> 1][(ni & 1) * 2 + 1]);
        }
    };

    // prologue: stage 0 (A via LDG+cvt+STS, B via cp.async)
    {
        float4 v[8];
        ldg_a2(0, 0, v[0], v[1]); ldg_a2(0, 1, v[2], v[3]);
        ldg_a2(0, 2, v[4], v[5]); ldg_a2(0, 3, v[6], v[7]);
        sts_a(0, 0, v[0], v[1]); sts_a(0, 1, v[2], v[3]);
        sts_a(0, 2, v[4], v[5]); sts_a(0, 3, v[6], v[7]);
        cp_b(0, 0);
        CP_COMMIT();
    }

    #pragma unroll
    for (int ks = 0; ks < NSTAGE; ks++) {
        const int buf = ks & 1;
        const int nbuf = buf ^ 1;
        const bool has_next = (ks < NSTAGE - 1);

        float4 pv[4];
        if (has_next) {            // prefetch A chunks 0,1 (regs) before the wait
            ldg_a2(ks + 1, 0, pv[0], pv[1]);
            ldg_a2(ks + 1, 1, pv[2], pv[3]);
        }

        CP_WAIT(0);                // current stage's B is the only pending group
        __syncthreads();           // single barrier: buf ready AND nbuf free

        if (has_next) {            // next stage's B in flight during compute
            cp_b(ks + 1, nbuf);
            CP_COMMIT();
        }

        const uint32_t sA = sbase + buf * STAGE_BYTES;
        const uint32_t sB = sA + A_BYTES;

        compute_half(sA, sB, 0);

        if (has_next) {
            sts_a(nbuf, 0, pv[0], pv[1]);
            sts_a(nbuf, 1, pv[2], pv[3]);
            ldg_a2(ks + 1, 2, pv[0], pv[1]);
            ldg_a2(ks + 1, 3, pv[2], pv[3]);
        }

        compute_half(sA, sB, 32);

        if (has_next) {
            sts_a(nbuf, 2, pv[0], pv[1]);
            sts_a(nbuf, 3, pv[2], pv[3]);
        }
    }

    // epilogue: g_xWsh[row] = half(raw * rsqrt(1 + cnt[row]))
    #pragma unroll
    for (int mi = 0; mi < 4; mi++) {
        int r0 = mbase + wm * 64 + mi * 16 + g;
        int r1 = r0 + 8;
        float dis0 = (r0 < n_nodes) ? rsqrtf(1.0f + (float)g_cnt[r0]) : 0.f;
        float dis1 = (r1 < n_nodes) ? rsqrtf(1.0f + (float)g_cnt[r1]) : 0.f;
        #pragma unroll
        for (int ni = 0; ni < 4; ni++) {
            int col = nbase + wn * 32 + ni * 8 + t * 2;
            if (r0 < n_nodes) {
                __half2 h = __floats2half2_rn(acc[mi][ni][0] * dis0, acc[mi][ni][1] * dis0);
                *(__half2*)(g_xWsh + (size_t)r0 * C + col) = h;
            }
            if (r1 < n_nodes) {
                __half2 h = __floats2half2_rn(acc[mi][ni][2] * dis1, acc[mi][ni][3] * dis1);
                *(__half2*)(g_xWsh + (size_t)r1 * C + col) = h;
            }
        }
    }
}

// ---------------------------------------------------------------------------
// Kernel 4: atomic-free gather over fp16 xWs. One warp per dst node.
// int4 adjacency loads + 8-edge unroll for deep MLP; HADD2 pairwise pre-add.
// out[d] = dis[d] * (xWs[d] + sum_{src in adj[d]} xWs[src]) + b
// ---------------------------------------------------------------------------
__global__ __launch_bounds__(256) void gather_kernel(
    const float* __restrict__ X, const float* __restrict__ b,
    const int* __restrict__ assign, float* __restrict__ out, int n_nodes) {
    int node = (blockIdx.x * blockDim.x + threadIdx.x) >> 5;
    int lane = threadIdx.x & 31;
    if (node >= n_nodes) return;

    if (g_cedge[assign[node]] == 0) {
        const float4* xrow = (const float4*)(X + (size_t)node * C);
        float4* orow = (float4*)(out + (size_t)node * C);
        orow[lane] = xrow[lane];
        orow[lane + 32] = xrow[lane + 32];
        return;
    }

    int cnt = g_cnt[node];
    if (cnt > CAP) cnt = CAP;
    float dis = rsqrtf(1.0f + (float)cnt);

    const uint4* xw = (const uint4*)g_xWsh;      // 16B = 8 halves per entry
    float a[8] = {0.f, 0.f, 0.f, 0.f, 0.f, 0.f, 0.f, 0.f};
    acc8(a, xw[(size_t)node * 32 + lane]);       // self term

    const int*  adj  = g_adj + (size_t)node * CAP;
    const int4* adj4 = (const int4*)adj;         // 256B-aligned rows
    int e = 0;
    for (; e + 8 <= cnt; e += 8) {               // 8 independent row loads in flight
        int4 q0 = adj4[e >> 2];
        int4 q1 = adj4[(e >> 2) + 1];
        uint4 v0 = xw[(size_t)q0.x * 32 + lane];
        uint4 v1 = xw[(size_t)q0.y * 32 + lane];
        uint4 v2 = xw[(size_t)q0.z * 32 + lane];
        uint4 v3 = xw[(size_t)q0.w * 32 + lane];
        uint4 v4 = xw[(size_t)q1.x * 32 + lane];
        uint4 v5 = xw[(size_t)q1.y * 32 + lane];
        uint4 v6 = xw[(size_t)q1.z * 32 + lane];
        uint4 v7 = xw[(size_t)q1.w * 32 + lane];
        acc8_pair(a, v0, v1);
        acc8_pair(a, v2, v3);
        acc8_pair(a, v4, v5);
        acc8_pair(a, v6, v7);
    }
    if (e + 4 <= cnt) {                          // e stays 4-aligned here
        int4 q = adj4[e >> 2];
        uint4 v0 = xw[(size_t)q.x * 32 + lane];
        uint4 v1 = xw[(size_t)q.y * 32 + lane];
        uint4 v2 = xw[(size_t)q.z * 32 + lane];
        uint4 v3 = xw[(size_t)q.w * 32 + lane];
        acc8_pair(a, v0, v1);
        acc8_pair(a, v2, v3);
        e += 4;
    }
    if (e + 2 <= cnt) {
        uint4 v0 = xw[(size_t)adj[e] * 32 + lane];
        uint4 v1 = xw[(size_t)adj[e + 1] * 32 + lane];
        acc8_pair(a, v0, v1);
        e += 2;
    }
    if (e < cnt)
        acc8(a, xw[(size_t)adj[e] * 32 + lane]);

    const float4* brow = (const float4*)b;       // lane owns floats [lane*8, lane*8+8)
    float4 b0 = brow[lane * 2], b1 = brow[lane * 2 + 1];
    float4 o0 = make_float4(a[0] * dis + b0.x, a[1] * dis + b0.y,
                            a[2] * dis + b0.z, a[3] * dis + b0.w);
    float4 o1 = make_float4(a[4] * dis + b1.x, a[5] * dis + b1.y,
                            a[6] * dis + b1.z, a[7] * dis + b1.w);
    float4* orow = (float4*)(out + (size_t)node * C + lane * 8);
    orow[0] = o0;
    orow[1] = o1;
}

// ---------------------------------------------------------------------------
extern "C" void kernel_launch(void* const* d_in, const int* in_sizes, int n_in,
                              void* d_out, int out_size) {
    const float* X      = (const float*)d_in[0];
    const float* W      = (const float*)d_in[1];
    const float* b      = (const float*)d_in[2];
    const int*   assign = (const int*)d_in[3];
    const int*   ei     = (const int*)d_in[4];

    int n_nodes = in_sizes[0] / C;
    int n_edges = in_sizes[4] / 2;
    const int* src = ei;
    const int* dst = ei + n_edges;
    float* out = (float*)d_out;

    cudaFuncSetAttribute(gemm_tc_kernel,
                         cudaFuncAttributeMaxDynamicSharedMemorySize, SMEM_TOTAL);

    init_wconv_kernel<<<NB_INIT + 64, 256>>>(W, n_nodes);
    edge_build_kernel<<<(n_edges + 255) / 256, 256>>>(src, dst, assign, n_edges);

    dim3 ggrid((n_nodes + BM - 1) / BM, C / BN);
    gemm_tc_kernel<<<ggrid, 256, SMEM_TOTAL>>>(X, n_nodes);

    int gth = n_nodes * 32;   // 1 warp per node
    gather_kernel<<<(gth + 255) / 256, 256>>>(X, b, assign, out, n_nodes);
}